// round 15
// baseline (speedup 1.0000x reference)
#include <cuda_runtime.h>
#include <cstdint>
#include <cuda_fp16.h>
#include <mma.h>

using namespace nvcuda;

#define HIDDEN 768
#define BATCH  4
#define SEQ    4096

// ---- scratch (device globals: allocation-free rule) ----
__device__ __half g_Q [BATCH * SEQ * HIDDEN];                // 24 MB (scale pre-folded)
__device__ __half g_K [BATCH * SEQ * HIDDEN];                // 24 MB
__device__ __half g_Vt[BATCH * HIDDEN * SEQ];                // 24 MB (V^T per batch)
__device__ __half g_S [(long long)BATCH * SEQ * SEQ];        // 128 MB (S then P, in place)
__device__ __half g_X [BATCH * SEQ * HIDDEN];                // 24 MB (fp16 x)
__device__ __half g_W [3 * HIDDEN * HIDDEN];                 // 3.5 MB (fp16 Wq|Wk|Wv)

// ===========================================================================
// FP16 wmma GEMM (fp32 accumulate):  C[M,N] = A[M,K] @ B^T (+bias)
// Block 128x128, 8 warps (256 thr, 2x4), warp tile 64x32, BK=64.
// 2-stage cp.async pipeline, 73.7KB smem -> 3 CTAs/SM (24 warps) under
// __launch_bounds__(256,3). Inner loop keeps B frags resident, streams A.
// ===========================================================================
constexpr int BM = 128, BN = 128, BK = 64;
constexpr int BKP = 72;                        // padded ld in halves (144B rows)

constexpr int TILE_H  = BM * BKP;              // 9216 halves per tile
constexpr int STAGE_H = 2 * TILE_H;            // A+B per stage
constexpr int NSTAGE  = 2;
constexpr int SMEM_B  = NSTAGE * STAGE_H * 2;  // 73728 bytes
constexpr int EPI_LD  = 36;                    // fp32 epilogue scratch ld (8*64*36*4 = 73728)

__device__ __forceinline__ void cp_async16(void* sdst, const void* gsrc) {
    unsigned int s = (unsigned int)__cvta_generic_to_shared(sdst);
    asm volatile("cp.async.cg.shared.global [%0], [%1], 16;\n" :: "r"(s), "l"(gsrc));
}
__device__ __forceinline__ void cp_commit() {
    asm volatile("cp.async.commit_group;\n");
}
template <int N_> __device__ __forceinline__ void cp_wait() {
    asm volatile("cp.async.wait_group %0;\n" :: "n"(N_));
}

// ---- shared mainloop: fills acc[4][2] for this CTA/warp ----
template <typename AccT>
__device__ __forceinline__ void gemm_mainloop(
    const __half* __restrict__ Ab, const __half* __restrict__ Bb,
    __half* smem, int K, int tid, int wm, int wn, AccT acc[4][2])
{
    auto load = [&](int stage, int t) {
        __half* As = smem + stage * STAGE_H;
        __half* Bs = As + TILE_H;
        const int kb = t * BK;
#pragma unroll
        for (int i = 0; i < 4; i++) {
            int idx = tid + (i << 8);
            int r = idx >> 3;
            int c = (idx & 7) << 3;
            cp_async16(&As[r * BKP + c], Ab + (long long)r * K + kb + c);
            cp_async16(&Bs[r * BKP + c], Bb + (long long)r * K + kb + c);
        }
        cp_commit();
    };

    const int T = K / BK;
    load(0, 0);
    if (T > 1) load(1, 1);

    for (int t = 0; t < T; t++) {
        if (t + 1 < T) cp_wait<1>();
        else           cp_wait<0>();
        __syncthreads();

        const int st = t & 1;
        const __half* As = smem + st * STAGE_H;
        const __half* Bs = As + TILE_H;

#pragma unroll
        for (int kk = 0; kk < BK; kk += 16) {
            // B fragments resident for this kk; A streamed per i (reg pressure)
            wmma::fragment<wmma::matrix_b, 16, 16, 16, __half, wmma::col_major> bf[2];
#pragma unroll
            for (int j = 0; j < 2; j++)
                wmma::load_matrix_sync(bf[j], &Bs[(wn + j * 16) * BKP + kk], BKP);
#pragma unroll
            for (int i = 0; i < 4; i++) {
                wmma::fragment<wmma::matrix_a, 16, 16, 16, __half, wmma::row_major> af;
                wmma::load_matrix_sync(af, &As[(wm + i * 16) * BKP + kk], BKP);
                wmma::mma_sync(acc[i][0], af, bf[0], acc[i][0]);
                wmma::mma_sync(acc[i][1], af, bf[1], acc[i][1]);
            }
        }
        __syncthreads();
        if (t + 2 < T) load(st, t + 2);
    }
}

// ---- generic GEMM: scores (HALF_OUT) and PV (fp32 out) ----
template <bool HALF_OUT>
__global__ __launch_bounds__(256, 3)
void h_gemm(const __half* __restrict__ A, const __half* __restrict__ B,
            float* __restrict__ Cf, __half* __restrict__ Ch,
            int N, int K,
            long long sA, long long sB, long long sC)
{
    extern __shared__ __half smem[];
    const int tid  = threadIdx.x;
    const int warp = tid >> 5;
    const int lane = tid & 31;
    const int m0 = blockIdx.y * BM;
    const int n0 = blockIdx.x * BN;
    const int z  = blockIdx.z;
    const int wm = (warp >> 2) * 64;
    const int wn = (warp & 3) * 32;

    const __half* Ab = A + z * sA + (long long)m0 * K;
    const __half* Bb = B + z * sB + (long long)n0 * K;

    wmma::fragment<wmma::accumulator, 16, 16, 16, float> acc[4][2];
#pragma unroll
    for (int i = 0; i < 4; i++)
#pragma unroll
        for (int j = 0; j < 2; j++)
            wmma::fill_fragment(acc[i][j], 0.0f);

    gemm_mainloop(Ab, Bb, smem, K, tid, wm, wn, acc);

    float* scr = (float*)smem + warp * (64 * EPI_LD);
#pragma unroll
    for (int i = 0; i < 4; i++)
#pragma unroll
        for (int j = 0; j < 2; j++)
            wmma::store_matrix_sync(&scr[(i * 16) * EPI_LD + j * 16], acc[i][j],
                                    EPI_LD, wmma::mem_row_major);
    __syncwarp();

    if constexpr (HALF_OUT) {
        __half* ch = Ch + z * sC;
#pragma unroll 8
        for (int r = 0; r < 64; r++)
            ch[(long long)(m0 + wm + r) * N + n0 + wn + lane] =
                __float2half_rn(scr[r * EPI_LD + lane]);
    } else {
        float* cf = Cf + z * sC;
#pragma unroll 8
        for (int r = 0; r < 64; r++)
            cf[(long long)(m0 + wm + r) * N + n0 + wn + lane] =
                scr[r * EPI_LD + lane];
    }
}

// ---- fused QKV: grid.z = 12 -> (w = z>>2: 0=Q,1=K,2=V ; b = z&3) ----
__global__ __launch_bounds__(256, 3)
void qkv_kernel(const __half* __restrict__ X, const __half* __restrict__ W3,
                __half* __restrict__ Q, __half* __restrict__ Kh,
                __half* __restrict__ Vt,
                const float* __restrict__ bq, const float* __restrict__ bk,
                const float* __restrict__ bv, float qscale)
{
    extern __shared__ __half smem[];
    const int tid  = threadIdx.x;
    const int warp = tid >> 5;
    const int lane = tid & 31;
    const int m0 = blockIdx.y * BM;
    const int n0 = blockIdx.x * BN;
    const int w  = blockIdx.z >> 2;          // 0=Q, 1=K, 2=V
    const int b  = blockIdx.z & 3;
    const int wm = (warp >> 2) * 64;
    const int wn = (warp & 3) * 32;

    const long long SH = (long long)SEQ * HIDDEN;
    const int WN = HIDDEN * HIDDEN;

    const __half* Ab = X + b * SH + (long long)m0 * HIDDEN;
    const __half* Bb = W3 + w * WN + (long long)n0 * HIDDEN;

    wmma::fragment<wmma::accumulator, 16, 16, 16, float> acc[4][2];
#pragma unroll
    for (int i = 0; i < 4; i++)
#pragma unroll
        for (int j = 0; j < 2; j++)
            wmma::fill_fragment(acc[i][j], 0.0f);

    gemm_mainloop(Ab, Bb, smem, HIDDEN, tid, wm, wn, acc);

    float* scr = (float*)smem + warp * (64 * EPI_LD);
#pragma unroll
    for (int i = 0; i < 4; i++)
#pragma unroll
        for (int j = 0; j < 2; j++)
            wmma::store_matrix_sync(&scr[(i * 16) * EPI_LD + j * 16], acc[i][j],
                                    EPI_LD, wmma::mem_row_major);
    __syncwarp();

    if (w == 2) {
        // V: transposed store -> Vt[b][h][s]; lanes sweep m (coalesced)
        __half* ct = Vt + b * SH;
        const int mA = m0 + wm + lane;
        const int mB = mA + 32;
#pragma unroll 4
        for (int j = 0; j < 32; j++) {
            float bb = bv[n0 + wn + j];
            long long rowo = (long long)(n0 + wn + j) * SEQ;
            ct[rowo + mA] = __float2half_rn(scr[lane * EPI_LD + j] + bb);
            ct[rowo + mB] = __float2half_rn(scr[(lane + 32) * EPI_LD + j] + bb);
        }
    } else {
        __half* ch = (w == 0 ? Q : Kh) + b * SH;
        const float* bias = (w == 0 ? bq : bk);
        const float sc = (w == 0 ? qscale : 1.0f);
        const float bb = bias[n0 + wn + lane];
#pragma unroll 8
        for (int r = 0; r < 64; r++)
            ch[(long long)(m0 + wm + r) * HIDDEN + n0 + wn + lane] =
                __float2half_rn((scr[r * EPI_LD + lane] + bb) * sc);
    }
}

// ---------------------------------------------------------------------------
// Convert fp32 -> fp16 (RN), vectorized.
// ---------------------------------------------------------------------------
__global__ void to_half_kernel(const float4* __restrict__ in,
                               __half2* __restrict__ out, int n4)
{
    int i = blockIdx.x * blockDim.x + threadIdx.x;
    if (i >= n4) return;
    float4 v = in[i];
    out[2 * i]     = __floats2half2_rn(v.x, v.y);
    out[2 * i + 1] = __floats2half2_rn(v.z, v.w);
}

// ---------------------------------------------------------------------------
// In-place row softmax over SEQ=4096 fp16 (scale pre-folded into Q).
// One block (256 thr) per row; half2 vectorized, fp32 math.
// ---------------------------------------------------------------------------
__global__ __launch_bounds__(256)
void softmax_kernel(__half* __restrict__ S)
{
    long long row = blockIdx.x;
    __half2* p = (__half2*)(S + row * (long long)SEQ);
    const int tid  = threadIdx.x;
    const int warp = tid >> 5;
    const int lane = tid & 31;

    __shared__ float red[8];
    __shared__ float bval;

    float v[16];
    float mx = -1e30f;
#pragma unroll
    for (int i = 0; i < 8; i++) {
        float2 f = __half22float2(p[i * 256 + tid]);
        v[2 * i] = f.x; v[2 * i + 1] = f.y;
        mx = fmaxf(mx, fmaxf(f.x, f.y));
    }
#pragma unroll
    for (int o = 16; o > 0; o >>= 1)
        mx = fmaxf(mx, __shfl_xor_sync(0xffffffffu, mx, o));
    if (lane == 0) red[warp] = mx;
    __syncthreads();
    if (tid == 0) {
        float m = red[0];
#pragma unroll
        for (int i = 1; i < 8; i++) m = fmaxf(m, red[i]);
        bval = m;
    }
    __syncthreads();
    mx = bval;
    __syncthreads();

    float sum = 0.0f;
#pragma unroll
    for (int i = 0; i < 16; i++) {
        v[i] = __expf(v[i] - mx);
        sum += v[i];
    }
#pragma unroll
    for (int o = 16; o > 0; o >>= 1)
        sum += __shfl_xor_sync(0xffffffffu, sum, o);
    if (lane == 0) red[warp] = sum;
    __syncthreads();
    if (tid == 0) {
        float s = 0.0f;
#pragma unroll
        for (int i = 0; i < 8; i++) s += red[i];
        bval = s;
    }
    __syncthreads();
    float inv = 1.0f / bval;
#pragma unroll
    for (int i = 0; i < 8; i++)
        p[i * 256 + tid] = __floats2half2_rn(v[2 * i] * inv, v[2 * i + 1] * inv);
}

// ---------------------------------------------------------------------------
// Launch
// ---------------------------------------------------------------------------
extern "C" void kernel_launch(void* const* d_in, const int* in_sizes, int n_in,
                              void* d_out, int out_size)
{
    const float* x  = (const float*)d_in[0];
    const float* Wq = (const float*)d_in[1];
    const float* bq = (const float*)d_in[2];
    const float* Wk = (const float*)d_in[3];
    const float* bk = (const float*)d_in[4];
    const float* Wv = (const float*)d_in[5];
    const float* bv = (const float*)d_in[6];
    float* out = (float*)d_out;

    __half *Qp, *Kp, *Vtp, *Sp, *Xp, *Wp;
    cudaGetSymbolAddress((void**)&Qp,  g_Q);
    cudaGetSymbolAddress((void**)&Kp,  g_K);
    cudaGetSymbolAddress((void**)&Vtp, g_Vt);
    cudaGetSymbolAddress((void**)&Sp,  g_S);
    cudaGetSymbolAddress((void**)&Xp,  g_X);
    cudaGetSymbolAddress((void**)&Wp,  g_W);

    cudaFuncSetAttribute((const void*)h_gemm<true>,
                         cudaFuncAttributeMaxDynamicSharedMemorySize, SMEM_B);
    cudaFuncSetAttribute((const void*)h_gemm<false>,
                         cudaFuncAttributeMaxDynamicSharedMemorySize, SMEM_B);
    cudaFuncSetAttribute((const void*)qkv_kernel,
                         cudaFuncAttributeMaxDynamicSharedMemorySize, SMEM_B);

    const long long SH = (long long)SEQ * HIDDEN;
    const long long SS = (long long)SEQ * SEQ;
    const int WN = HIDDEN * HIDDEN;

    // 0) convert inputs to fp16
    {
        int n4x = BATCH * SEQ * HIDDEN / 4;
        to_half_kernel<<<(n4x + 255) / 256, 256>>>((const float4*)x, (__half2*)Xp, n4x);
        int n4w = WN / 4;
        to_half_kernel<<<(n4w + 255) / 256, 256>>>((const float4*)Wq, (__half2*)(Wp), n4w);
        to_half_kernel<<<(n4w + 255) / 256, 256>>>((const float4*)Wk, (__half2*)(Wp + WN), n4w);
        to_half_kernel<<<(n4w + 255) / 256, 256>>>((const float4*)Wv, (__half2*)(Wp + 2 * WN), n4w);
    }

    // 1) fused QKV: one launch, grid.z = 12 (3 weights x 4 batches).
    //    Q gets softmax scale folded in; V stored transposed.
    {
        float qscale = 1.0f / sqrtf((float)HIDDEN);
        dim3 g(HIDDEN / BN, SEQ / BM, 12);      // (6, 32, 12)
        qkv_kernel<<<g, 256, SMEM_B>>>(Xp, Wp, Qp, Kp, Vtp, bq, bk, bv, qscale);
    }

    // 2+3) per batch: scores_b (fp16 S, scaled) then in-place softmax_b.
    //      S_b is 32 MB fp16 -> L2-resident between the two launches.
    for (int b = 0; b < BATCH; b++) {
        dim3 g(SEQ / BN, SEQ / BM, 1);          // (32, 32)
        h_gemm<true><<<g, 256, SMEM_B>>>(Qp + b * SH, Kp + b * SH,
                                         nullptr, Sp + b * SS,
                                         SEQ, HIDDEN, 0, 0, 0);
        softmax_kernel<<<SEQ, 256>>>(Sp + b * SS);
    }

    // 4) output: O_b = P_b @ V_b   (Vt is [HIDDEN, SEQ] K-major, K = SEQ)
    {
        dim3 g(HIDDEN / BN, SEQ / BM, BATCH);   // (6, 32, 4)
        h_gemm<false><<<g, 256, SMEM_B>>>(Sp, Vtp, out, nullptr,
                                          HIDDEN, SEQ, SS, SH, SH);
    }
}

// round 16
// speedup vs baseline: 1.8091x; 1.8091x over previous
#include <cuda_runtime.h>
#include <cstdint>
#include <cuda_fp16.h>
#include <mma.h>

using namespace nvcuda;

#define HIDDEN 768
#define BATCH  4
#define SEQ    4096

// ---- scratch (device globals: allocation-free rule) ----
__device__ __half g_Q [BATCH * SEQ * HIDDEN];                // 24 MB (scale pre-folded)
__device__ __half g_K [BATCH * SEQ * HIDDEN];                // 24 MB
__device__ __half g_Vt[BATCH * HIDDEN * SEQ];                // 24 MB (V^T per batch)
__device__ __half g_S [(long long)BATCH * SEQ * SEQ];        // 128 MB (S then P, in place)
__device__ __half g_X [BATCH * SEQ * HIDDEN];                // 24 MB (fp16 x)
__device__ __half g_W [3 * HIDDEN * HIDDEN];                 // 3.5 MB (fp16 Wq|Wk|Wv)

// ===========================================================================
// FP16 wmma GEMM (fp32 accumulate):  C[M,N] = A[M,K] @ B^T (+bias)
// Block 128x128, 8 warps (256 thr, 2x4), warp tile 64x32, BK=64,
// 3-stage cp.async pipeline, 2 CTAs/SM. (Measured optimum: R14, 916 us.)
// ===========================================================================
constexpr int BM = 128, BN = 128, BK = 64;
constexpr int BKP = 72;                        // padded ld in halves (144B rows)

constexpr int TILE_H  = BM * BKP;              // 9216 halves per tile
constexpr int STAGE_H = 2 * TILE_H;            // A+B per stage
constexpr int NSTAGE  = 3;
constexpr int SMEM_B  = NSTAGE * STAGE_H * 2;  // 110592 bytes
constexpr int EPI_LD  = 36;                    // fp32 epilogue scratch ld

__device__ __forceinline__ void cp_async16(void* sdst, const void* gsrc) {
    unsigned int s = (unsigned int)__cvta_generic_to_shared(sdst);
    asm volatile("cp.async.cg.shared.global [%0], [%1], 16;\n" :: "r"(s), "l"(gsrc));
}
__device__ __forceinline__ void cp_commit() {
    asm volatile("cp.async.commit_group;\n");
}
template <int N_> __device__ __forceinline__ void cp_wait() {
    asm volatile("cp.async.wait_group %0;\n" :: "n"(N_));
}

// ---- shared mainloop: fills acc[4][2] for this CTA/warp ----
template <typename AccT>
__device__ __forceinline__ void gemm_mainloop(
    const __half* __restrict__ Ab, const __half* __restrict__ Bb,
    __half* smem, int K, int tid, int wm, int wn, AccT acc[4][2])
{
    auto load = [&](int stage, int t) {
        __half* As = smem + stage * STAGE_H;
        __half* Bs = As + TILE_H;
        const int kb = t * BK;
#pragma unroll
        for (int i = 0; i < 4; i++) {
            int idx = tid + (i << 8);
            int r = idx >> 3;
            int c = (idx & 7) << 3;
            cp_async16(&As[r * BKP + c], Ab + (long long)r * K + kb + c);
            cp_async16(&Bs[r * BKP + c], Bb + (long long)r * K + kb + c);
        }
        cp_commit();
    };

    const int T = K / BK;
    load(0, 0);
    load(1, 1);
    load(2, 2);

    for (int t = 0; t < T; t++) {
        const int rem = T - 1 - t;
        if (rem >= 2)      cp_wait<2>();
        else if (rem == 1) cp_wait<1>();
        else               cp_wait<0>();
        __syncthreads();

        const int st = t % 3;
        const __half* As = smem + st * STAGE_H;
        const __half* Bs = As + TILE_H;

#pragma unroll
        for (int kk = 0; kk < BK; kk += 16) {
            wmma::fragment<wmma::matrix_a, 16, 16, 16, __half, wmma::row_major> af[4];
            wmma::fragment<wmma::matrix_b, 16, 16, 16, __half, wmma::col_major> bf[2];
#pragma unroll
            for (int i = 0; i < 4; i++)
                wmma::load_matrix_sync(af[i], &As[(wm + i * 16) * BKP + kk], BKP);
#pragma unroll
            for (int j = 0; j < 2; j++)
                wmma::load_matrix_sync(bf[j], &Bs[(wn + j * 16) * BKP + kk], BKP);
#pragma unroll
            for (int i = 0; i < 4; i++)
#pragma unroll
                for (int j = 0; j < 2; j++)
                    wmma::mma_sync(acc[i][j], af[i], bf[j], acc[i][j]);
        }
        __syncthreads();
        if (t + 3 < T) load(st, t + 3);
    }
}

// ---- generic GEMM: scores (HALF_OUT) and PV (fp32 out) ----
template <bool HALF_OUT>
__global__ __launch_bounds__(256, 2)
void h_gemm(const __half* __restrict__ A, const __half* __restrict__ B,
            float* __restrict__ Cf, __half* __restrict__ Ch,
            int N, int K,
            long long sA, long long sB, long long sC)
{
    extern __shared__ __half smem[];
    const int tid  = threadIdx.x;
    const int warp = tid >> 5;
    const int lane = tid & 31;
    const int m0 = blockIdx.y * BM;
    const int n0 = blockIdx.x * BN;
    const int z  = blockIdx.z;
    const int wm = (warp >> 2) * 64;
    const int wn = (warp & 3) * 32;

    const __half* Ab = A + z * sA + (long long)m0 * K;
    const __half* Bb = B + z * sB + (long long)n0 * K;

    wmma::fragment<wmma::accumulator, 16, 16, 16, float> acc[4][2];
#pragma unroll
    for (int i = 0; i < 4; i++)
#pragma unroll
        for (int j = 0; j < 2; j++)
            wmma::fill_fragment(acc[i][j], 0.0f);

    gemm_mainloop(Ab, Bb, smem, K, tid, wm, wn, acc);

    float* scr = (float*)smem + warp * (64 * EPI_LD);
#pragma unroll
    for (int i = 0; i < 4; i++)
#pragma unroll
        for (int j = 0; j < 2; j++)
            wmma::store_matrix_sync(&scr[(i * 16) * EPI_LD + j * 16], acc[i][j],
                                    EPI_LD, wmma::mem_row_major);
    __syncwarp();

    if constexpr (HALF_OUT) {
        __half* ch = Ch + z * sC;
#pragma unroll 8
        for (int r = 0; r < 64; r++)
            ch[(long long)(m0 + wm + r) * N + n0 + wn + lane] =
                __float2half_rn(scr[r * EPI_LD + lane]);
    } else {
        float* cf = Cf + z * sC;
#pragma unroll 8
        for (int r = 0; r < 64; r++)
            cf[(long long)(m0 + wm + r) * N + n0 + wn + lane] =
                scr[r * EPI_LD + lane];
    }
}

// ---- fused QKV: grid.z = 12 -> (w = z>>2: 0=Q,1=K,2=V ; b = z&3) ----
__global__ __launch_bounds__(256, 2)
void qkv_kernel(const __half* __restrict__ X, const __half* __restrict__ W3,
                __half* __restrict__ Q, __half* __restrict__ Kh,
                __half* __restrict__ Vt,
                const float* __restrict__ bq, const float* __restrict__ bk,
                const float* __restrict__ bv, float qscale)
{
    extern __shared__ __half smem[];
    const int tid  = threadIdx.x;
    const int warp = tid >> 5;
    const int lane = tid & 31;
    const int m0 = blockIdx.y * BM;
    const int n0 = blockIdx.x * BN;
    const int w  = blockIdx.z >> 2;          // 0=Q, 1=K, 2=V
    const int b  = blockIdx.z & 3;
    const int wm = (warp >> 2) * 64;
    const int wn = (warp & 3) * 32;

    const long long SH = (long long)SEQ * HIDDEN;
    const int WN = HIDDEN * HIDDEN;

    const __half* Ab = X + b * SH + (long long)m0 * HIDDEN;
    const __half* Bb = W3 + w * WN + (long long)n0 * HIDDEN;

    wmma::fragment<wmma::accumulator, 16, 16, 16, float> acc[4][2];
#pragma unroll
    for (int i = 0; i < 4; i++)
#pragma unroll
        for (int j = 0; j < 2; j++)
            wmma::fill_fragment(acc[i][j], 0.0f);

    gemm_mainloop(Ab, Bb, smem, HIDDEN, tid, wm, wn, acc);

    float* scr = (float*)smem + warp * (64 * EPI_LD);
#pragma unroll
    for (int i = 0; i < 4; i++)
#pragma unroll
        for (int j = 0; j < 2; j++)
            wmma::store_matrix_sync(&scr[(i * 16) * EPI_LD + j * 16], acc[i][j],
                                    EPI_LD, wmma::mem_row_major);
    __syncwarp();

    if (w == 2) {
        // V: transposed store -> Vt[b][h][s]; lanes sweep m (coalesced)
        __half* ct = Vt + b * SH;
        const int mA = m0 + wm + lane;
        const int mB = mA + 32;
#pragma unroll 4
        for (int j = 0; j < 32; j++) {
            float bb = bv[n0 + wn + j];
            long long rowo = (long long)(n0 + wn + j) * SEQ;
            ct[rowo + mA] = __float2half_rn(scr[lane * EPI_LD + j] + bb);
            ct[rowo + mB] = __float2half_rn(scr[(lane + 32) * EPI_LD + j] + bb);
        }
    } else {
        __half* ch = (w == 0 ? Q : Kh) + b * SH;
        const float* bias = (w == 0 ? bq : bk);
        const float sc = (w == 0 ? qscale : 1.0f);
        const float bb = bias[n0 + wn + lane];
#pragma unroll 8
        for (int r = 0; r < 64; r++)
            ch[(long long)(m0 + wm + r) * HIDDEN + n0 + wn + lane] =
                __float2half_rn((scr[r * EPI_LD + lane] + bb) * sc);
    }
}

// ---------------------------------------------------------------------------
// Convert fp32 -> fp16 (RN), vectorized.
// ---------------------------------------------------------------------------
__global__ void to_half_kernel(const float4* __restrict__ in,
                               __half2* __restrict__ out, int n4)
{
    int i = blockIdx.x * blockDim.x + threadIdx.x;
    if (i >= n4) return;
    float4 v = in[i];
    out[2 * i]     = __floats2half2_rn(v.x, v.y);
    out[2 * i + 1] = __floats2half2_rn(v.z, v.w);
}

// ---------------------------------------------------------------------------
// In-place row softmax over SEQ=4096 fp16 (scale pre-folded into Q).
// One block (256 thr) per row; half2 vectorized, fp32 math.
// ---------------------------------------------------------------------------
__global__ __launch_bounds__(256)
void softmax_kernel(__half* __restrict__ S)
{
    long long row = blockIdx.x;
    __half2* p = (__half2*)(S + row * (long long)SEQ);
    const int tid  = threadIdx.x;
    const int warp = tid >> 5;
    const int lane = tid & 31;

    __shared__ float red[8];
    __shared__ float bval;

    float v[16];
    float mx = -1e30f;
#pragma unroll
    for (int i = 0; i < 8; i++) {
        float2 f = __half22float2(p[i * 256 + tid]);
        v[2 * i] = f.x; v[2 * i + 1] = f.y;
        mx = fmaxf(mx, fmaxf(f.x, f.y));
    }
#pragma unroll
    for (int o = 16; o > 0; o >>= 1)
        mx = fmaxf(mx, __shfl_xor_sync(0xffffffffu, mx, o));
    if (lane == 0) red[warp] = mx;
    __syncthreads();
    if (tid == 0) {
        float m = red[0];
#pragma unroll
        for (int i = 1; i < 8; i++) m = fmaxf(m, red[i]);
        bval = m;
    }
    __syncthreads();
    mx = bval;
    __syncthreads();

    float sum = 0.0f;
#pragma unroll
    for (int i = 0; i < 16; i++) {
        v[i] = __expf(v[i] - mx);
        sum += v[i];
    }
#pragma unroll
    for (int o = 16; o > 0; o >>= 1)
        sum += __shfl_xor_sync(0xffffffffu, sum, o);
    if (lane == 0) red[warp] = sum;
    __syncthreads();
    if (tid == 0) {
        float s = 0.0f;
#pragma unroll
        for (int i = 0; i < 8; i++) s += red[i];
        bval = s;
    }
    __syncthreads();
    float inv = 1.0f / bval;
#pragma unroll
    for (int i = 0; i < 8; i++)
        p[i * 256 + tid] = __floats2half2_rn(v[2 * i] * inv, v[2 * i + 1] * inv);
}

// ---------------------------------------------------------------------------
// Launch
// ---------------------------------------------------------------------------
extern "C" void kernel_launch(void* const* d_in, const int* in_sizes, int n_in,
                              void* d_out, int out_size)
{
    const float* x  = (const float*)d_in[0];
    const float* Wq = (const float*)d_in[1];
    const float* bq = (const float*)d_in[2];
    const float* Wk = (const float*)d_in[3];
    const float* bk = (const float*)d_in[4];
    const float* Wv = (const float*)d_in[5];
    const float* bv = (const float*)d_in[6];
    float* out = (float*)d_out;

    __half *Qp, *Kp, *Vtp, *Sp, *Xp, *Wp;
    cudaGetSymbolAddress((void**)&Qp,  g_Q);
    cudaGetSymbolAddress((void**)&Kp,  g_K);
    cudaGetSymbolAddress((void**)&Vtp, g_Vt);
    cudaGetSymbolAddress((void**)&Sp,  g_S);
    cudaGetSymbolAddress((void**)&Xp,  g_X);
    cudaGetSymbolAddress((void**)&Wp,  g_W);

    cudaFuncSetAttribute((const void*)h_gemm<true>,
                         cudaFuncAttributeMaxDynamicSharedMemorySize, SMEM_B);
    cudaFuncSetAttribute((const void*)h_gemm<false>,
                         cudaFuncAttributeMaxDynamicSharedMemorySize, SMEM_B);
    cudaFuncSetAttribute((const void*)qkv_kernel,
                         cudaFuncAttributeMaxDynamicSharedMemorySize, SMEM_B);

    const long long SH = (long long)SEQ * HIDDEN;
    const long long SS = (long long)SEQ * SEQ;
    const int WN = HIDDEN * HIDDEN;

    // 0) convert inputs to fp16
    {
        int n4x = BATCH * SEQ * HIDDEN / 4;
        to_half_kernel<<<(n4x + 255) / 256, 256>>>((const float4*)x, (__half2*)Xp, n4x);
        int n4w = WN / 4;
        to_half_kernel<<<(n4w + 255) / 256, 256>>>((const float4*)Wq, (__half2*)(Wp), n4w);
        to_half_kernel<<<(n4w + 255) / 256, 256>>>((const float4*)Wk, (__half2*)(Wp + WN), n4w);
        to_half_kernel<<<(n4w + 255) / 256, 256>>>((const float4*)Wv, (__half2*)(Wp + 2 * WN), n4w);
    }

    // 1) fused QKV: one launch, grid.z = 12 (3 weights x 4 batches).
    //    Q gets softmax scale folded in; V stored transposed.
    {
        float qscale = 1.0f / sqrtf((float)HIDDEN);
        dim3 g(HIDDEN / BN, SEQ / BM, 12);      // (6, 32, 12)
        qkv_kernel<<<g, 256, SMEM_B>>>(Xp, Wp, Qp, Kp, Vtp, bq, bk, bv, qscale);
    }

    // 2+3) per batch: scores_b (fp16 S, scaled) then in-place softmax_b.
    //      S_b is 32 MB fp16 -> L2-resident between the two launches.
    for (int b = 0; b < BATCH; b++) {
        dim3 g(SEQ / BN, SEQ / BM, 1);          // (32, 32)
        h_gemm<true><<<g, 256, SMEM_B>>>(Qp + b * SH, Kp + b * SH,
                                         nullptr, Sp + b * SS,
                                         SEQ, HIDDEN, 0, 0, 0);
        softmax_kernel<<<SEQ, 256>>>(Sp + b * SS);
    }

    // 4) output: O_b = P_b @ V_b   (Vt is [HIDDEN, SEQ] K-major, K = SEQ)
    {
        dim3 g(HIDDEN / BN, SEQ / BM, BATCH);   // (6, 32, 4)
        h_gemm<false><<<g, 256, SMEM_B>>>(Sp, Vtp, out, nullptr,
                                          HIDDEN, SEQ, SS, SH, SH);
    }
}